// round 15
// baseline (speedup 1.0000x reference)
#include <cuda_runtime.h>
#include <cuda_fp16.h>

static constexpr int MAX_NC = 50000;
static constexpr int MAX_NG = 3000;
static constexpr int D      = 64;

// cg relation (cell->gene): 4 sub-buckets per gene (keeps per-address atomic
// pressure low; verified correct in R13).
static constexpr int SUB_CG       = 4;
static constexpr int SUBSTRIDE_CG = 384;
static constexpr int STRIDE_GC    = 128;   // gene->cell, degree ~60
static constexpr int STRIDE_GG    = 96;    // gene->gene, degree ~33

// fp16 weighted source features (wf = feat * cj * mask); row = 128 B.
__device__ __half g_wf_c[MAX_NC * D];
__device__ __half g_wf_grev[MAX_NG * D];
__device__ __half g_wf_ggg[MAX_NG * D];

// Buckets + cursors.
__device__ int g_bkt_cg[MAX_NG * SUB_CG * SUBSTRIDE_CG];
__device__ int g_bkt_gc[MAX_NC * STRIDE_GC];
__device__ int g_bkt_gg[MAX_NG * STRIDE_GG];
__device__ int g_cnt_cg[MAX_NG * SUB_CG];
__device__ int g_cnt_gc[MAX_NC];
__device__ int g_cnt_gg[MAX_NG];

// ---------------------------------------------------------------------------
// Fused weighting: one kernel covers the cell table (1 weighting) and the
// gene table (2 weightings) via thread-range partition.
// ---------------------------------------------------------------------------
__global__ void weight_fused(const float* __restrict__ c_feat,
                             const float* __restrict__ cj_c, const float* __restrict__ m_c,
                             __half* __restrict__ out_c, int nv_c,
                             const float* __restrict__ g_feat,
                             const float* __restrict__ cj1, const float* __restrict__ m1,
                             const float* __restrict__ cj2, const float* __restrict__ m2,
                             __half* __restrict__ out1, __half* __restrict__ out2,
                             int nv_g) {
    int i = blockIdx.x * blockDim.x + threadIdx.x;
    if (i < nv_c) {
        int row = i >> 4;
        float w = __ldg(cj_c + row) * __ldg(m_c + row);
        float4 v = __ldg(((const float4*)c_feat) + i);
        ((__half2*)out_c)[i * 2 + 0] = __floats2half2_rn(v.x * w, v.y * w);
        ((__half2*)out_c)[i * 2 + 1] = __floats2half2_rn(v.z * w, v.w * w);
    } else if (i < nv_c + nv_g) {
        int j = i - nv_c;
        int row = j >> 4;
        float4 v = __ldg(((const float4*)g_feat) + j);
        float w1 = __ldg(cj1 + row) * __ldg(m1 + row);
        float w2 = __ldg(cj2 + row) * __ldg(m2 + row);
        ((__half2*)out1)[j * 2 + 0] = __floats2half2_rn(v.x * w1, v.y * w1);
        ((__half2*)out1)[j * 2 + 1] = __floats2half2_rn(v.z * w1, v.w * w1);
        ((__half2*)out2)[j * 2 + 0] = __floats2half2_rn(v.x * w2, v.y * w2);
        ((__half2*)out2)[j * 2 + 1] = __floats2half2_rn(v.z * w2, v.w * w2);
    }
}

// ---------------------------------------------------------------------------
// Bucket build core: 4 edges per thread, nsub sub-counters per destination.
// ---------------------------------------------------------------------------
__device__ __forceinline__ void build4(const int* __restrict__ src,
                                       const int* __restrict__ dst,
                                       int* __restrict__ cnt,
                                       int* __restrict__ bkt,
                                       int nsub, int substride, int nE,
                                       int t /* relation-local thread idx */) {
    int e0 = t * 4;
    if (e0 >= nE) return;
    int sub = t & (nsub - 1);

    if (e0 + 4 <= nE) {
        int4 s4 = __ldg((const int4*)(src + e0));
        int4 d4 = __ldg((const int4*)(dst + e0));
        int s[4] = {s4.x, s4.y, s4.z, s4.w};
        int d[4] = {d4.x, d4.y, d4.z, d4.w};
        int pos[4];
        #pragma unroll
        for (int k = 0; k < 4; k++)
            pos[k] = atomicAdd(cnt + d[k] * nsub + sub, 1);
        #pragma unroll
        for (int k = 0; k < 4; k++)
            if (pos[k] < substride)
                bkt[((size_t)d[k] * nsub + sub) * substride + pos[k]] = s[k];
    } else {
        for (int e = e0; e < nE; e++) {
            int d = __ldg(dst + e);
            int pos = atomicAdd(cnt + d * nsub + sub, 1);
            if (pos < substride)
                bkt[((size_t)d * nsub + sub) * substride + pos] = __ldg(src + e);
        }
    }
}

// Fused build: one grid covers all three relations (latency overlap).
__global__ void bucket_build_fused(
        const int* __restrict__ src_cg, const int* __restrict__ dst_cg,
        int* __restrict__ cnt_cg, int* __restrict__ bkt_cg, int e_cg,
        const int* __restrict__ src_gc, const int* __restrict__ dst_gc,
        int* __restrict__ cnt_gc, int* __restrict__ bkt_gc, int e_gc,
        const int* __restrict__ src_gg, const int* __restrict__ dst_gg,
        int* __restrict__ cnt_gg, int* __restrict__ bkt_gg, int e_gg) {
    int t = blockIdx.x * blockDim.x + threadIdx.x;
    int T1 = (e_cg + 3) / 4;
    int T2 = (e_gc + 3) / 4;
    int T3 = (e_gg + 3) / 4;
    if (t < T1) {
        build4(src_cg, dst_cg, cnt_cg, bkt_cg, SUB_CG, SUBSTRIDE_CG, e_cg, t);
    } else if (t < T1 + T2) {
        build4(src_gc, dst_gc, cnt_gc, bkt_gc, 1, STRIDE_GC, e_gc, t - T1);
    } else if (t < T1 + T2 + T3) {
        build4(src_gg, dst_gg, cnt_gg, bkt_gg, 1, STRIDE_GG, e_gg, t - T1 - T2);
    }
}

// ---------------------------------------------------------------------------
// Warp segment accumulate, software-pipelined (double-buffered 8-deep).
// Lane owns dims [2*lane, 2*lane+1]. Walks chunks chunk0, chunk0+step, ...
// ---------------------------------------------------------------------------
__device__ __forceinline__ void warp_seg_accum_strided(
        const int* __restrict__ bkt_seg, int n, int chunk0, int chunk_step,
        const __half* __restrict__ wf, int lane, float& ax, float& ay) {
    for (int i = chunk0 * 32; i < n; i += chunk_step * 32) {
        int m = n - i; if (m > 32) m = 32;
        int my = (lane < m) ? __ldg(bkt_seg + i + lane) : 0;

        if (m == 32) {
            unsigned cur[8], nxt[8];
            #pragma unroll
            for (int j = 0; j < 8; j++) {
                int s = __shfl_sync(0xffffffffu, my, j);
                cur[j] = __ldg((const unsigned*)(wf + (size_t)s * D) + lane);
            }
            #pragma unroll
            for (int k = 8; k <= 32; k += 8) {
                if (k < 32) {
                    #pragma unroll
                    for (int j = 0; j < 8; j++) {
                        int s = __shfl_sync(0xffffffffu, my, k + j);
                        nxt[j] = __ldg((const unsigned*)(wf + (size_t)s * D) + lane);
                    }
                }
                #pragma unroll
                for (int j = 0; j < 8; j++) {
                    float2 f = __half22float2(*reinterpret_cast<const __half2*>(&cur[j]));
                    ax += f.x; ay += f.y;
                }
                #pragma unroll
                for (int j = 0; j < 8; j++) cur[j] = nxt[j];
            }
        } else {
            int k = 0;
            for (; k + 8 <= m; k += 8) {
                unsigned r[8];
                #pragma unroll
                for (int j = 0; j < 8; j++) {
                    int s = __shfl_sync(0xffffffffu, my, k + j);
                    r[j] = __ldg((const unsigned*)(wf + (size_t)s * D) + lane);
                }
                #pragma unroll
                for (int j = 0; j < 8; j++) {
                    float2 f = __half22float2(*reinterpret_cast<const __half2*>(&r[j]));
                    ax += f.x; ay += f.y;
                }
            }
            for (; k < m; k++) {
                int s = __shfl_sync(0xffffffffu, my, k);
                unsigned r = __ldg((const unsigned*)(wf + (size_t)s * D) + lane);
                float2 f = __half22float2(*reinterpret_cast<const __half2*>(&r));
                ax += f.x; ay += f.y;
            }
        }
    }
}

// ---------------------------------------------------------------------------
// Fused pull: blocks [0, ng) = gene path (8 warps cooperate on one gene);
// blocks [ng, ...) = cell path (each of the 8 warps owns one cell).
// ---------------------------------------------------------------------------
__global__ void __launch_bounds__(256)
pull_fused(const int* __restrict__ bkt_cg, const int* __restrict__ cnt_cg,
           const int* __restrict__ bkt_gg, const int* __restrict__ cnt_gg,
           const int* __restrict__ bkt_gc, const int* __restrict__ cnt_gc,
           const __half* __restrict__ wf_c, const __half* __restrict__ wf_gg,
           const __half* __restrict__ wf_grev,
           const float* __restrict__ ci_g, const float* __restrict__ cii_g,
           const float* __restrict__ ci_c,
           float* __restrict__ g_out, float* __restrict__ c_out,
           int ng, int nc) {
    int wid  = threadIdx.x >> 5;
    int lane = threadIdx.x & 31;

    if (blockIdx.x < (unsigned)ng) {
        // ---- gene path: one block per gene ----
        __shared__ float sA[8][D];
        __shared__ float sB[8][D];
        int g = blockIdx.x;

        float ax = 0.f, ay = 0.f, bx = 0.f, by = 0.f;
        #pragma unroll
        for (int sub = 0; sub < SUB_CG; sub++) {
            int n = __ldg(cnt_cg + g * SUB_CG + sub);
            if (n > SUBSTRIDE_CG) n = SUBSTRIDE_CG;
            warp_seg_accum_strided(bkt_cg + ((size_t)g * SUB_CG + sub) * SUBSTRIDE_CG,
                                   n, wid, 8, wf_c, lane, ax, ay);
        }
        {
            int n = __ldg(cnt_gg + g); if (n > STRIDE_GG) n = STRIDE_GG;
            warp_seg_accum_strided(bkt_gg + (size_t)g * STRIDE_GG, n, wid, 8,
                                   wf_gg, lane, bx, by);
        }

        sA[wid][2 * lane]     = ax;
        sA[wid][2 * lane + 1] = ay;
        sB[wid][2 * lane]     = bx;
        sB[wid][2 * lane + 1] = by;
        __syncthreads();

        if (threadIdx.x < D) {
            int t = threadIdx.x;
            float sa = 0.f, sb = 0.f;
            #pragma unroll
            for (int w = 0; w < 8; w++) { sa += sA[w][t]; sb += sB[w][t]; }
            float w1 = 0.5f * __ldg(ci_g + g);
            float w2 = 0.5f * __ldg(cii_g + g);
            g_out[(size_t)g * D + t] = sa * w1 + sb * w2;
        }
    } else {
        // ---- cell path: 8 warps, one cell per warp ----
        int cell = (blockIdx.x - ng) * 8 + wid;
        if (cell >= nc) return;

        float ax = 0.f, ay = 0.f;
        int n = __ldg(cnt_gc + cell); if (n > STRIDE_GC) n = STRIDE_GC;
        warp_seg_accum_strided(bkt_gc + (size_t)cell * STRIDE_GC, n, 0, 1,
                               wf_grev, lane, ax, ay);

        float w = __ldg(ci_c + cell);
        ((float2*)(c_out + (size_t)cell * D))[lane] = make_float2(ax * w, ay * w);
    }
}

// ---------------------------------------------------------------------------
// kernel_launch
// Inputs: c_feat, g_feat, cj_cell, ci_cell, cj_gene, ci_gene, cjj_gene,
//   cii_gene, mask_exp, mask_rev, mask_gg,
//   src_cg, dst_cg, src_gc, dst_gc, src_gg, dst_gg
// Output: concat(c_out [NC*D], g_out [NG*D]) float32.
// ---------------------------------------------------------------------------
extern "C" void kernel_launch(void* const* d_in, const int* in_sizes, int n_in,
                              void* d_out, int out_size) {
    const float* c_feat   = (const float*)d_in[0];
    const float* g_feat   = (const float*)d_in[1];
    const float* cj_cell  = (const float*)d_in[2];
    const float* ci_cell  = (const float*)d_in[3];
    const float* cj_gene  = (const float*)d_in[4];
    const float* ci_gene  = (const float*)d_in[5];
    const float* cjj_gene = (const float*)d_in[6];
    const float* cii_gene = (const float*)d_in[7];
    const float* mask_exp = (const float*)d_in[8];
    const float* mask_rev = (const float*)d_in[9];
    const float* mask_gg  = (const float*)d_in[10];
    const int*   src_cg   = (const int*)d_in[11];
    const int*   dst_cg   = (const int*)d_in[12];
    const int*   src_gc   = (const int*)d_in[13];
    const int*   dst_gc   = (const int*)d_in[14];
    const int*   src_gg   = (const int*)d_in[15];
    const int*   dst_gg   = (const int*)d_in[16];

    const int nc   = in_sizes[0] / D;
    const int ng   = in_sizes[1] / D;
    const int e_cg = in_sizes[11];
    const int e_gc = in_sizes[13];
    const int e_gg = in_sizes[15];

    float* c_out = (float*)d_out;                  // [nc, D]
    float* g_out = (float*)d_out + (size_t)nc * D; // [ng, D]

    __half *wf_c, *wf_grev, *wf_ggg;
    int *bkt_cg, *bkt_gc, *bkt_gg, *cnt_cg, *cnt_gc, *cnt_gg;
    cudaGetSymbolAddress((void**)&wf_c,    g_wf_c);
    cudaGetSymbolAddress((void**)&wf_grev, g_wf_grev);
    cudaGetSymbolAddress((void**)&wf_ggg,  g_wf_ggg);
    cudaGetSymbolAddress((void**)&bkt_cg,  g_bkt_cg);
    cudaGetSymbolAddress((void**)&bkt_gc,  g_bkt_gc);
    cudaGetSymbolAddress((void**)&bkt_gg,  g_bkt_gg);
    cudaGetSymbolAddress((void**)&cnt_cg,  g_cnt_cg);
    cudaGetSymbolAddress((void**)&cnt_gc,  g_cnt_gc);
    cudaGetSymbolAddress((void**)&cnt_gg,  g_cnt_gg);

    // 1) zero the bucket cursors
    cudaMemsetAsync(cnt_cg, 0, (size_t)ng * SUB_CG * sizeof(int));
    cudaMemsetAsync(cnt_gc, 0, (size_t)nc * sizeof(int));
    cudaMemsetAsync(cnt_gg, 0, (size_t)ng * sizeof(int));

    // 2) fused fp16 weighting (cell + gene tables in one launch)
    {
        int nv_c = nc * (D / 4);
        int nv_g = ng * (D / 4);
        int total = nv_c + nv_g;
        weight_fused<<<(total + 255) / 256, 256>>>(
            c_feat, cj_cell, mask_exp, wf_c, nv_c,
            g_feat, cj_gene, mask_rev, cjj_gene, mask_gg,
            wf_grev, wf_ggg, nv_g);
    }

    // 3) fused bucket build (all three relations overlap in one grid)
    {
        long long T = (long long)((e_cg + 3) / 4) + (e_gc + 3) / 4 + (e_gg + 3) / 4;
        int blocks = (int)((T + 255) / 256);
        bucket_build_fused<<<blocks, 256>>>(
            src_cg, dst_cg, cnt_cg, bkt_cg, e_cg,
            src_gc, dst_gc, cnt_gc, bkt_gc, e_gc,
            src_gg, dst_gg, cnt_gg, bkt_gg, e_gg);
    }

    // 4) fused pull (gene blocks + cell blocks in one grid)
    {
        int cell_blocks = (nc + 7) / 8;
        pull_fused<<<ng + cell_blocks, 256>>>(
            bkt_cg, cnt_cg, bkt_gg, cnt_gg, bkt_gc, cnt_gc,
            wf_c, wf_ggg, wf_grev,
            ci_gene, cii_gene, ci_cell,
            g_out, c_out, ng, nc);
    }
}

// round 16
// speedup vs baseline: 1.0012x; 1.0012x over previous
#include <cuda_runtime.h>
#include <cuda_fp16.h>

static constexpr int MAX_NC = 50000;
static constexpr int MAX_NG = 3000;
static constexpr int D      = 64;

// cg relation (cell->gene): 4 sub-buckets per gene (keeps per-address atomic
// pressure low; verified correct in R13).
static constexpr int SUB_CG       = 4;
static constexpr int SUBSTRIDE_CG = 384;
static constexpr int STRIDE_GC    = 128;   // gene->cell, degree ~60
static constexpr int STRIDE_GG    = 96;    // gene->gene, degree ~33

// fp16 weighted source features (wf = feat * cj * mask); row = 128 B.
__device__ __half g_wf_c[MAX_NC * D];
__device__ __half g_wf_grev[MAX_NG * D];
__device__ __half g_wf_ggg[MAX_NG * D];

// Buckets + cursors.
__device__ int g_bkt_cg[MAX_NG * SUB_CG * SUBSTRIDE_CG];
__device__ int g_bkt_gc[MAX_NC * STRIDE_GC];
__device__ int g_bkt_gg[MAX_NG * STRIDE_GG];
__device__ int g_cnt_cg[MAX_NG * SUB_CG];
__device__ int g_cnt_gc[MAX_NC];
__device__ int g_cnt_gg[MAX_NG];

// ---------------------------------------------------------------------------
// Fused weighting: one kernel covers the cell table (1 weighting) and the
// gene table (2 weightings) via thread-range partition.
// ---------------------------------------------------------------------------
__global__ void weight_fused(const float* __restrict__ c_feat,
                             const float* __restrict__ cj_c, const float* __restrict__ m_c,
                             __half* __restrict__ out_c, int nv_c,
                             const float* __restrict__ g_feat,
                             const float* __restrict__ cj1, const float* __restrict__ m1,
                             const float* __restrict__ cj2, const float* __restrict__ m2,
                             __half* __restrict__ out1, __half* __restrict__ out2,
                             int nv_g) {
    int i = blockIdx.x * blockDim.x + threadIdx.x;
    if (i < nv_c) {
        int row = i >> 4;
        float w = __ldg(cj_c + row) * __ldg(m_c + row);
        float4 v = __ldg(((const float4*)c_feat) + i);
        ((__half2*)out_c)[i * 2 + 0] = __floats2half2_rn(v.x * w, v.y * w);
        ((__half2*)out_c)[i * 2 + 1] = __floats2half2_rn(v.z * w, v.w * w);
    } else if (i < nv_c + nv_g) {
        int j = i - nv_c;
        int row = j >> 4;
        float4 v = __ldg(((const float4*)g_feat) + j);
        float w1 = __ldg(cj1 + row) * __ldg(m1 + row);
        float w2 = __ldg(cj2 + row) * __ldg(m2 + row);
        ((__half2*)out1)[j * 2 + 0] = __floats2half2_rn(v.x * w1, v.y * w1);
        ((__half2*)out1)[j * 2 + 1] = __floats2half2_rn(v.z * w1, v.w * w1);
        ((__half2*)out2)[j * 2 + 0] = __floats2half2_rn(v.x * w2, v.y * w2);
        ((__half2*)out2)[j * 2 + 1] = __floats2half2_rn(v.z * w2, v.w * w2);
    }
}

// ---------------------------------------------------------------------------
// Bucket build core: 4 edges per thread, nsub sub-counters per destination.
// ---------------------------------------------------------------------------
__device__ __forceinline__ void build4(const int* __restrict__ src,
                                       const int* __restrict__ dst,
                                       int* __restrict__ cnt,
                                       int* __restrict__ bkt,
                                       int nsub, int substride, int nE,
                                       int t /* relation-local thread idx */) {
    int e0 = t * 4;
    if (e0 >= nE) return;
    int sub = t & (nsub - 1);

    if (e0 + 4 <= nE) {
        int4 s4 = __ldg((const int4*)(src + e0));
        int4 d4 = __ldg((const int4*)(dst + e0));
        int s[4] = {s4.x, s4.y, s4.z, s4.w};
        int d[4] = {d4.x, d4.y, d4.z, d4.w};
        int pos[4];
        #pragma unroll
        for (int k = 0; k < 4; k++)
            pos[k] = atomicAdd(cnt + d[k] * nsub + sub, 1);
        #pragma unroll
        for (int k = 0; k < 4; k++)
            if (pos[k] < substride)
                bkt[((size_t)d[k] * nsub + sub) * substride + pos[k]] = s[k];
    } else {
        for (int e = e0; e < nE; e++) {
            int d = __ldg(dst + e);
            int pos = atomicAdd(cnt + d * nsub + sub, 1);
            if (pos < substride)
                bkt[((size_t)d * nsub + sub) * substride + pos] = __ldg(src + e);
        }
    }
}

// Fused build: one grid covers all three relations (latency overlap).
__global__ void bucket_build_fused(
        const int* __restrict__ src_cg, const int* __restrict__ dst_cg,
        int* __restrict__ cnt_cg, int* __restrict__ bkt_cg, int e_cg,
        const int* __restrict__ src_gc, const int* __restrict__ dst_gc,
        int* __restrict__ cnt_gc, int* __restrict__ bkt_gc, int e_gc,
        const int* __restrict__ src_gg, const int* __restrict__ dst_gg,
        int* __restrict__ cnt_gg, int* __restrict__ bkt_gg, int e_gg) {
    int t = blockIdx.x * blockDim.x + threadIdx.x;
    int T1 = (e_cg + 3) / 4;
    int T2 = (e_gc + 3) / 4;
    int T3 = (e_gg + 3) / 4;
    if (t < T1) {
        build4(src_cg, dst_cg, cnt_cg, bkt_cg, SUB_CG, SUBSTRIDE_CG, e_cg, t);
    } else if (t < T1 + T2) {
        build4(src_gc, dst_gc, cnt_gc, bkt_gc, 1, STRIDE_GC, e_gc, t - T1);
    } else if (t < T1 + T2 + T3) {
        build4(src_gg, dst_gg, cnt_gg, bkt_gg, 1, STRIDE_GG, e_gg, t - T1 - T2);
    }
}

// ---------------------------------------------------------------------------
// Warp segment accumulate, software-pipelined (double-buffered 8-deep).
// Lane owns dims [2*lane, 2*lane+1]. Walks chunks chunk0, chunk0+step, ...
// ---------------------------------------------------------------------------
__device__ __forceinline__ void warp_seg_accum_strided(
        const int* __restrict__ bkt_seg, int n, int chunk0, int chunk_step,
        const __half* __restrict__ wf, int lane, float& ax, float& ay) {
    for (int i = chunk0 * 32; i < n; i += chunk_step * 32) {
        int m = n - i; if (m > 32) m = 32;
        int my = (lane < m) ? __ldg(bkt_seg + i + lane) : 0;

        if (m == 32) {
            unsigned cur[8], nxt[8];
            #pragma unroll
            for (int j = 0; j < 8; j++) {
                int s = __shfl_sync(0xffffffffu, my, j);
                cur[j] = __ldg((const unsigned*)(wf + (size_t)s * D) + lane);
            }
            #pragma unroll
            for (int k = 8; k <= 32; k += 8) {
                if (k < 32) {
                    #pragma unroll
                    for (int j = 0; j < 8; j++) {
                        int s = __shfl_sync(0xffffffffu, my, k + j);
                        nxt[j] = __ldg((const unsigned*)(wf + (size_t)s * D) + lane);
                    }
                }
                #pragma unroll
                for (int j = 0; j < 8; j++) {
                    float2 f = __half22float2(*reinterpret_cast<const __half2*>(&cur[j]));
                    ax += f.x; ay += f.y;
                }
                #pragma unroll
                for (int j = 0; j < 8; j++) cur[j] = nxt[j];
            }
        } else {
            int k = 0;
            for (; k + 8 <= m; k += 8) {
                unsigned r[8];
                #pragma unroll
                for (int j = 0; j < 8; j++) {
                    int s = __shfl_sync(0xffffffffu, my, k + j);
                    r[j] = __ldg((const unsigned*)(wf + (size_t)s * D) + lane);
                }
                #pragma unroll
                for (int j = 0; j < 8; j++) {
                    float2 f = __half22float2(*reinterpret_cast<const __half2*>(&r[j]));
                    ax += f.x; ay += f.y;
                }
            }
            for (; k < m; k++) {
                int s = __shfl_sync(0xffffffffu, my, k);
                unsigned r = __ldg((const unsigned*)(wf + (size_t)s * D) + lane);
                float2 f = __half22float2(*reinterpret_cast<const __half2*>(&r));
                ax += f.x; ay += f.y;
            }
        }
    }
}

// ---------------------------------------------------------------------------
// Fused pull: blocks [0, ng) = gene path (8 warps cooperate on one gene);
// blocks [ng, ...) = cell path (each of the 8 warps owns one cell).
// ---------------------------------------------------------------------------
__global__ void __launch_bounds__(256)
pull_fused(const int* __restrict__ bkt_cg, const int* __restrict__ cnt_cg,
           const int* __restrict__ bkt_gg, const int* __restrict__ cnt_gg,
           const int* __restrict__ bkt_gc, const int* __restrict__ cnt_gc,
           const __half* __restrict__ wf_c, const __half* __restrict__ wf_gg,
           const __half* __restrict__ wf_grev,
           const float* __restrict__ ci_g, const float* __restrict__ cii_g,
           const float* __restrict__ ci_c,
           float* __restrict__ g_out, float* __restrict__ c_out,
           int ng, int nc) {
    int wid  = threadIdx.x >> 5;
    int lane = threadIdx.x & 31;

    if (blockIdx.x < (unsigned)ng) {
        // ---- gene path: one block per gene ----
        __shared__ float sA[8][D];
        __shared__ float sB[8][D];
        int g = blockIdx.x;

        float ax = 0.f, ay = 0.f, bx = 0.f, by = 0.f;
        #pragma unroll
        for (int sub = 0; sub < SUB_CG; sub++) {
            int n = __ldg(cnt_cg + g * SUB_CG + sub);
            if (n > SUBSTRIDE_CG) n = SUBSTRIDE_CG;
            warp_seg_accum_strided(bkt_cg + ((size_t)g * SUB_CG + sub) * SUBSTRIDE_CG,
                                   n, wid, 8, wf_c, lane, ax, ay);
        }
        {
            int n = __ldg(cnt_gg + g); if (n > STRIDE_GG) n = STRIDE_GG;
            warp_seg_accum_strided(bkt_gg + (size_t)g * STRIDE_GG, n, wid, 8,
                                   wf_gg, lane, bx, by);
        }

        sA[wid][2 * lane]     = ax;
        sA[wid][2 * lane + 1] = ay;
        sB[wid][2 * lane]     = bx;
        sB[wid][2 * lane + 1] = by;
        __syncthreads();

        if (threadIdx.x < D) {
            int t = threadIdx.x;
            float sa = 0.f, sb = 0.f;
            #pragma unroll
            for (int w = 0; w < 8; w++) { sa += sA[w][t]; sb += sB[w][t]; }
            float w1 = 0.5f * __ldg(ci_g + g);
            float w2 = 0.5f * __ldg(cii_g + g);
            g_out[(size_t)g * D + t] = sa * w1 + sb * w2;
        }
    } else {
        // ---- cell path: 8 warps, one cell per warp ----
        int cell = (blockIdx.x - ng) * 8 + wid;
        if (cell >= nc) return;

        float ax = 0.f, ay = 0.f;
        int n = __ldg(cnt_gc + cell); if (n > STRIDE_GC) n = STRIDE_GC;
        warp_seg_accum_strided(bkt_gc + (size_t)cell * STRIDE_GC, n, 0, 1,
                               wf_grev, lane, ax, ay);

        float w = __ldg(ci_c + cell);
        ((float2*)(c_out + (size_t)cell * D))[lane] = make_float2(ax * w, ay * w);
    }
}

// ---------------------------------------------------------------------------
// kernel_launch
// Inputs: c_feat, g_feat, cj_cell, ci_cell, cj_gene, ci_gene, cjj_gene,
//   cii_gene, mask_exp, mask_rev, mask_gg,
//   src_cg, dst_cg, src_gc, dst_gc, src_gg, dst_gg
// Output: concat(c_out [NC*D], g_out [NG*D]) float32.
// ---------------------------------------------------------------------------
extern "C" void kernel_launch(void* const* d_in, const int* in_sizes, int n_in,
                              void* d_out, int out_size) {
    const float* c_feat   = (const float*)d_in[0];
    const float* g_feat   = (const float*)d_in[1];
    const float* cj_cell  = (const float*)d_in[2];
    const float* ci_cell  = (const float*)d_in[3];
    const float* cj_gene  = (const float*)d_in[4];
    const float* ci_gene  = (const float*)d_in[5];
    const float* cjj_gene = (const float*)d_in[6];
    const float* cii_gene = (const float*)d_in[7];
    const float* mask_exp = (const float*)d_in[8];
    const float* mask_rev = (const float*)d_in[9];
    const float* mask_gg  = (const float*)d_in[10];
    const int*   src_cg   = (const int*)d_in[11];
    const int*   dst_cg   = (const int*)d_in[12];
    const int*   src_gc   = (const int*)d_in[13];
    const int*   dst_gc   = (const int*)d_in[14];
    const int*   src_gg   = (const int*)d_in[15];
    const int*   dst_gg   = (const int*)d_in[16];

    const int nc   = in_sizes[0] / D;
    const int ng   = in_sizes[1] / D;
    const int e_cg = in_sizes[11];
    const int e_gc = in_sizes[13];
    const int e_gg = in_sizes[15];

    float* c_out = (float*)d_out;                  // [nc, D]
    float* g_out = (float*)d_out + (size_t)nc * D; // [ng, D]

    __half *wf_c, *wf_grev, *wf_ggg;
    int *bkt_cg, *bkt_gc, *bkt_gg, *cnt_cg, *cnt_gc, *cnt_gg;
    cudaGetSymbolAddress((void**)&wf_c,    g_wf_c);
    cudaGetSymbolAddress((void**)&wf_grev, g_wf_grev);
    cudaGetSymbolAddress((void**)&wf_ggg,  g_wf_ggg);
    cudaGetSymbolAddress((void**)&bkt_cg,  g_bkt_cg);
    cudaGetSymbolAddress((void**)&bkt_gc,  g_bkt_gc);
    cudaGetSymbolAddress((void**)&bkt_gg,  g_bkt_gg);
    cudaGetSymbolAddress((void**)&cnt_cg,  g_cnt_cg);
    cudaGetSymbolAddress((void**)&cnt_gc,  g_cnt_gc);
    cudaGetSymbolAddress((void**)&cnt_gg,  g_cnt_gg);

    // 1) zero the bucket cursors
    cudaMemsetAsync(cnt_cg, 0, (size_t)ng * SUB_CG * sizeof(int));
    cudaMemsetAsync(cnt_gc, 0, (size_t)nc * sizeof(int));
    cudaMemsetAsync(cnt_gg, 0, (size_t)ng * sizeof(int));

    // 2) fused fp16 weighting (cell + gene tables in one launch)
    {
        int nv_c = nc * (D / 4);
        int nv_g = ng * (D / 4);
        int total = nv_c + nv_g;
        weight_fused<<<(total + 255) / 256, 256>>>(
            c_feat, cj_cell, mask_exp, wf_c, nv_c,
            g_feat, cj_gene, mask_rev, cjj_gene, mask_gg,
            wf_grev, wf_ggg, nv_g);
    }

    // 3) fused bucket build (all three relations overlap in one grid)
    {
        long long T = (long long)((e_cg + 3) / 4) + (e_gc + 3) / 4 + (e_gg + 3) / 4;
        int blocks = (int)((T + 255) / 256);
        bucket_build_fused<<<blocks, 256>>>(
            src_cg, dst_cg, cnt_cg, bkt_cg, e_cg,
            src_gc, dst_gc, cnt_gc, bkt_gc, e_gc,
            src_gg, dst_gg, cnt_gg, bkt_gg, e_gg);
    }

    // 4) fused pull (gene blocks + cell blocks in one grid)
    {
        int cell_blocks = (nc + 7) / 8;
        pull_fused<<<ng + cell_blocks, 256>>>(
            bkt_cg, cnt_cg, bkt_gg, cnt_gg, bkt_gc, cnt_gc,
            wf_c, wf_ggg, wf_grev,
            ci_gene, cii_gene, ci_cell,
            g_out, c_out, ng, nc);
    }
}